// round 14
// baseline (speedup 1.0000x reference)
#include <cuda_runtime.h>
#include <cuda_bf16.h>
#include <cstdint>

#define SEQ 1600
#define BH  64
#define OUT_ELEMS (8*SEQ*512)

// -------------------- scratch --------------------
__device__ __nv_bfloat16 g_qh[(size_t)BH*SEQ*64];
__device__ __nv_bfloat16 g_ql[(size_t)BH*SEQ*64];
__device__ __nv_bfloat16 g_kh[(size_t)BH*SEQ*64];
__device__ __nv_bfloat16 g_kl[(size_t)BH*SEQ*64];
__device__ __nv_bfloat16 g_vh[(size_t)BH*SEQ*64];   // [bh][s][d] natural
__device__ __nv_bfloat16 g_vl[(size_t)BH*SEQ*64];
__device__ __nv_bfloat16 g_wth[3*512*256];          // [mat][n][k] transposed
__device__ __nv_bfloat16 g_wtl[3*512*256];
__device__ float g_rowinv[(size_t)BH*SEQ];
__device__ int   g_done[8];

// -------------------- mma.sync / ldmatrix --------------------
__device__ __forceinline__ uint32_t smem_u32(const void* p_) {
    uint32_t a;
    asm("{ .reg .u64 t; cvta.to.shared.u64 t, %1; cvt.u32.u64 %0, t; }" : "=r"(a) : "l"(p_));
    return a;
}
__device__ __forceinline__ void ldsm4(uint32_t* r, uint32_t addr) {
    asm volatile("ldmatrix.sync.aligned.m8n8.x4.shared.b16 {%0,%1,%2,%3}, [%4];"
                 : "=r"(r[0]), "=r"(r[1]), "=r"(r[2]), "=r"(r[3]) : "r"(addr));
}
__device__ __forceinline__ void ldsm4t(uint32_t* r, uint32_t addr) {
    asm volatile("ldmatrix.sync.aligned.m8n8.x4.trans.shared.b16 {%0,%1,%2,%3}, [%4];"
                 : "=r"(r[0]), "=r"(r[1]), "=r"(r[2]), "=r"(r[3]) : "r"(addr));
}
__device__ __forceinline__ void mma16816(float* d, const uint32_t* a, const uint32_t* b) {
    asm volatile("mma.sync.aligned.m16n8k16.row.col.f32.bf16.bf16.f32 "
                 "{%0,%1,%2,%3}, {%4,%5,%6,%7}, {%8,%9}, {%0,%1,%2,%3};"
                 : "+f"(d[0]), "+f"(d[1]), "+f"(d[2]), "+f"(d[3])
                 : "r"(a[0]), "r"(a[1]), "r"(a[2]), "r"(a[3]), "r"(b[0]), "r"(b[1]));
}
__device__ __forceinline__ void split2(float a, float b, uint32_t& hi, uint32_t& lo) {
    __nv_bfloat162 h = __float22bfloat162_rn(make_float2(a, b));
    float2 hf = __bfloat1622float2(h);
    __nv_bfloat162 l = __float22bfloat162_rn(make_float2(a - hf.x, b - hf.y));
    hi = *(uint32_t*)&h; lo = *(uint32_t*)&l;
}

// -------------------- norm slice helper --------------------
__device__ __forceinline__ void norm_slice(int nc, int idx, float* __restrict__ p, int tid)
{
    const int base_row = nc*12800 + idx*64;
    float4* pb = (float4*)p + (size_t)base_row*400;
    const float* ri = g_rowinv + base_row;
    #pragma unroll 4
    for (int j = 0; j < 200; j++) {
        const int fi = j*128 + tid;
        const float rv = ri[fi/400];
        float4 v = pb[fi];
        v.x *= rv; v.y *= rv; v.z *= rv; v.w *= rv;
        pb[fi] = v;
    }
}

// ==================== K0: transpose + split W (+ zero counters) ====================
__global__ __launch_bounds__(256) void convert_w_kernel(
    const float* __restrict__ wq, const float* __restrict__ wk, const float* __restrict__ wv)
{
    const int idx = blockIdx.x*256 + threadIdx.x;
    if (idx < 8) g_done[idx] = 0;
    const int mat = idx >> 17;
    const int rem = idx & 131071;
    const float* w = (mat == 0) ? wq : ((mat == 1) ? wk : wv);
    const float v = w[rem];
    __nv_bfloat16 h = __float2bfloat16(v);
    __nv_bfloat16 l = __float2bfloat16(v - __bfloat162float(h));
    const int k = rem >> 9, n = rem & 511;
    const size_t off = ((size_t)mat << 17) + (size_t)n*256 + k;
    g_wth[off] = h; g_wtl[off] = l;
}

// ==================== K1: QKV projection via mma ====================
#define PJ_TILE 9216
#define PJ_SMEM_BYTES (4*PJ_TILE*2)

__global__ __launch_bounds__(256, 2) void proj_kernel(
    const float* __restrict__ x,
    const float* __restrict__ bq, const float* __restrict__ bk, const float* __restrict__ bv)
{
    extern __shared__ __align__(16) __nv_bfloat16 sm[];
    __nv_bfloat16* XH = sm;
    __nv_bfloat16* XL = sm + PJ_TILE;
    __nv_bfloat16* WH = sm + 2*PJ_TILE;
    __nv_bfloat16* WL = sm + 3*PJ_TILE;

    const int tid = threadIdx.x, w = tid >> 5, lane = tid & 31;
    const int m0 = blockIdx.x*128, n0 = blockIdx.y*128, mat = blockIdx.z;
    const float* bb = (mat == 0) ? bq : ((mat == 1) ? bk : bv);
    const __nv_bfloat16* wth = g_wth + ((size_t)mat << 17);
    const __nv_bfloat16* wtl = g_wtl + ((size_t)mat << 17);

    float acc[16][4];
    #pragma unroll
    for (int i = 0; i < 16; i++)
        #pragma unroll
        for (int j = 0; j < 4; j++) acc[i][j] = 0.f;

    const uint32_t aXH = smem_u32(XH), aXL = smem_u32(XL);
    const uint32_t aWH = smem_u32(WH), aWL = smem_u32(WL);

    const int arow = lane & 15, ak8 = (lane >> 4)*8;
    const int mi = lane >> 3, l8 = lane & 7;
    const int brow8 = (mi >> 1)*8 + l8, bk8 = (mi & 1)*8;

    for (int kc = 0; kc < 256; kc += 64) {
        #pragma unroll
        for (int j = 0; j < 8; j++) {
            const int idx = tid + j*256;
            const int r = idx >> 4, c4 = idx & 15;
            const float4 v = *(const float4*)&x[(size_t)(m0 + r)*256 + kc + c4*4];
            uint32_t h01, l01, h23, l23;
            split2(v.x, v.y, h01, l01);
            split2(v.z, v.w, h23, l23);
            *(uint2*)&XH[r*72 + c4*4] = make_uint2(h01, h23);
            *(uint2*)&XL[r*72 + c4*4] = make_uint2(l01, l23);
        }
        #pragma unroll
        for (int j = 0; j < 4; j++) {
            const int idx = tid + j*256;
            const int r = idx >> 3, c8 = (idx & 7)*8;
            const size_t off = (size_t)(n0 + r)*256 + kc + c8;
            *(uint4*)&WH[r*72 + c8] = *(const uint4*)&wth[off];
            *(uint4*)&WL[r*72 + c8] = *(const uint4*)&wtl[off];
        }
        __syncthreads();

        #pragma unroll
        for (int kc16 = 0; kc16 < 4; kc16++) {
            uint32_t ah[4], al[4];
            const uint32_t aoff = (uint32_t)(((w*16 + arow)*72 + kc16*16 + ak8)*2);
            ldsm4(ah, aXH + aoff);
            ldsm4(al, aXL + aoff);
            #pragma unroll
            for (int nbp = 0; nbp < 8; nbp++) {
                uint32_t bhf[4], blf[4];
                const uint32_t boff = (uint32_t)(((nbp*16 + brow8)*72 + kc16*16 + bk8)*2);
                ldsm4(bhf, aWH + boff);
                ldsm4(blf, aWL + boff);
                #pragma unroll
                for (int half = 0; half < 2; half++) {
                    const int nb = nbp*2 + half, sel = half*2;
                    mma16816(acc[nb], ah, &bhf[sel]);
                    mma16816(acc[nb], ah, &blf[sel]);
                    mma16816(acc[nb], al, &bhf[sel]);
                }
            }
        }
        __syncthreads();
    }

    const int r0 = lane >> 2, c0 = (lane & 3)*2;
    const int m1 = m0 + w*16 + r0, m2 = m1 + 8;
    const int bI1 = m1 / SEQ, s1 = m1 % SEQ;
    const int bI2 = m2 / SEQ, s2 = m2 % SEQ;
    const float sc = (mat == 0) ? 0.125f : 1.0f;
    __nv_bfloat16* dh = (mat == 0) ? g_qh : ((mat == 1) ? g_kh : g_vh);
    __nv_bfloat16* dl = (mat == 0) ? g_ql : ((mat == 1) ? g_kl : g_vl);

    #pragma unroll
    for (int nb = 0; nb < 16; nb++) {
        const int n = n0 + nb*8 + c0;
        const int h = n >> 6, d = n & 63;
        const float b0 = bb[n], b1 = bb[n + 1];
        #pragma unroll
        for (int rr = 0; rr < 2; rr++) {
            float v0 = acc[nb][rr*2]     + b0;
            float v1 = acc[nb][rr*2 + 1] + b1;
            v0 *= sc; v1 *= sc;
            if (mat == 2) { v0 = fmaxf(v0, 0.f); v1 = fmaxf(v1, 0.f); }
            uint32_t hi, lo;
            split2(v0, v1, hi, lo);
            const int bI = rr ? bI2 : bI1;
            const int s  = rr ? s2  : s1;
            const size_t off = ((size_t)(bI*8 + h)*SEQ + s)*64 + d;
            *(uint32_t*)&dh[off] = hi;
            *(uint32_t*)&dl[off] = lo;
        }
    }
}

// ==================== K2: fused attention + deferred norm tail ====================
// 2000 blocks: 0..1599 fused (chunk=bid/200), 1600..1999 norm-only (chunks 6,7).
// Fused block of chunk i >= 2 normalizes slice idx of chunk i-2 after its epilogue.
#define FA_TILE 4608
#define FA_SMEM_BYTES (6*FA_TILE*2)

__global__ __launch_bounds__(128) void attn_combined_kernel(float* __restrict__ p,
                                                            float* __restrict__ out)
{
    const int bid = blockIdx.x;
    const int tid = threadIdx.x;

    if (bid >= 1600) {
        // ---------------- trailing norm-only role (chunks 6, 7) ----------------
        const int j2 = bid - 1600;
        const int nc = 6 + (j2 >= 200 ? 1 : 0);
        const int idx = j2 % 200;
        if (tid == 0) {
            while (atomicAdd(&g_done[nc], 0) < 200) __nanosleep(256);
            __threadfence();
        }
        __syncthreads();
        norm_slice(nc, idx, p, tid);
        return;
    }

    const int chunk = bid / 200;
    const int idx = bid % 200;

    // ---------------- fused role (round-9 q64 geometry) ----------------
    extern __shared__ __align__(16) __nv_bfloat16 sm[];
    __nv_bfloat16* QH = sm;
    __nv_bfloat16* QL = sm + FA_TILE;
    __nv_bfloat16* KH = sm + 2*FA_TILE;
    __nv_bfloat16* KL = sm + 3*FA_TILE;
    __nv_bfloat16* VH = sm + 4*FA_TILE;
    __nv_bfloat16* VL = sm + 5*FA_TILE;

    const int w = tid >> 5, lane = tid & 31;
    const int qt = idx % 25, bh = chunk*8 + idx/25;
    const int q0 = qt*64;

    {
        const uint4* sqh = (const uint4*)(g_qh + ((size_t)bh*SEQ + q0)*64);
        const uint4* sql = (const uint4*)(g_ql + ((size_t)bh*SEQ + q0)*64);
        #pragma unroll
        for (int it = 0; it < 4; it++) {
            const int i = tid + it*128;
            const int r = i >> 3, c8 = (i & 7)*8;
            *(uint4*)&QH[r*72 + c8] = sqh[i];
            *(uint4*)&QL[r*72 + c8] = sql[i];
        }
    }

    const uint32_t aQH = smem_u32(QH), aQL = smem_u32(QL);
    const uint32_t aKH = smem_u32(KH), aKL = smem_u32(KL);
    const uint32_t aVH = smem_u32(VH), aVL = smem_u32(VL);

    const int arow = lane & 15, ak8 = (lane >> 4)*8;
    const int mi = lane >> 3, l8 = lane & 7;
    const int brow8 = (mi >> 1)*8 + l8, bk8 = (mi & 1)*8;
    const int tk8 = (mi & 1)*8, tn8 = (mi >> 1)*8;
    const int r0 = lane >> 2, c0 = (lane & 3)*2;

    const int q1 = q0 + w*16 + r0, q2 = q1 + 8;
    const int qf1 = q1 / 25, qf2 = q2 / 25;
    float* prow1 = p + ((size_t)bh*SEQ + q1)*SEQ;
    float* prow2 = p + ((size_t)bh*SEQ + q2)*SEQ;

    float acc_out[8][4];
    #pragma unroll
    for (int i = 0; i < 8; i++)
        #pragma unroll
        for (int j = 0; j < 4; j++) acc_out[i][j] = 0.f;
    float s1 = 0.f, s2 = 0.f;

    for (int c = 0; c < 25; c++) {
        const int s0 = c*64;
        #pragma unroll
        for (int it = 0; it < 4; it++) {
            const int i = tid + it*128;
            const int r = i >> 3, c8 = (i & 7)*8;
            const size_t gs = ((size_t)bh*SEQ + s0 + r)*64 + c8;
            *(uint4*)&KH[r*72 + c8] = *(const uint4*)&g_kh[gs];
            *(uint4*)&KL[r*72 + c8] = *(const uint4*)&g_kl[gs];
            *(uint4*)&VH[r*72 + c8] = *(const uint4*)&g_vh[gs];
            *(uint4*)&VL[r*72 + c8] = *(const uint4*)&g_vl[gs];
        }
        __syncthreads();

        // ---- QK^T ----
        float eacc[8][4];
        #pragma unroll
        for (int i = 0; i < 8; i++)
            #pragma unroll
            for (int j = 0; j < 4; j++) eacc[i][j] = 0.f;

        #pragma unroll
        for (int kc = 0; kc < 4; kc++) {
            uint32_t ah[4], al[4], bkh[4][4], bkl[4][4];
            const uint32_t aoff = (uint32_t)(((w*16 + arow)*72 + kc*16 + ak8)*2);
            ldsm4(ah, aQH + aoff);
            ldsm4(al, aQL + aoff);
            #pragma unroll
            for (int nbp = 0; nbp < 4; nbp++) {
                const uint32_t boff = (uint32_t)(((nbp*16 + brow8)*72 + kc*16 + bk8)*2);
                ldsm4(bkh[nbp], aKH + boff);
                ldsm4(bkl[nbp], aKL + boff);
            }
            #pragma unroll
            for (int nb = 0; nb < 8; nb++) {
                const int nbp = nb >> 1, sel = (nb & 1)*2;
                mma16816(eacc[nb], ah, &bkh[nbp][sel]);
                mma16816(eacc[nb], ah, &bkl[nbp][sel]);
                mma16816(eacc[nb], al, &bkh[nbp][sel]);
            }
        }

        // ---- mask + exp + store raw e + rowsum ----
        #pragma unroll
        for (int nb = 0; nb < 8; nb++) {
            const int k = s0 + nb*8 + c0;
            const int kfa = k / 25, kfb = (k + 1) / 25;
            float e0 = (qf1 != kfa || q1 == k  ) ? __expf(eacc[nb][0]) : 0.f;
            float e1 = (qf1 != kfb || q1 == k+1) ? __expf(eacc[nb][1]) : 0.f;
            float e2 = (qf2 != kfa || q2 == k  ) ? __expf(eacc[nb][2]) : 0.f;
            float e3 = (qf2 != kfb || q2 == k+1) ? __expf(eacc[nb][3]) : 0.f;
            s1 += e0 + e1; s2 += e2 + e3;
            *(float2*)&prow1[k] = make_float2(e0, e1);
            *(float2*)&prow2[k] = make_float2(e2, e3);
            eacc[nb][0] = e0; eacc[nb][1] = e1; eacc[nb][2] = e2; eacc[nb][3] = e3;
        }

        // ---- PV ----
        #pragma unroll
        for (int kc2 = 0; kc2 < 4; kc2++) {
            uint32_t ahx[4], alx[4];
            #pragma unroll
            for (int half = 0; half < 2; half++) {
                const float* e4 = eacc[kc2*2 + half];
                uint32_t h01, l01, h23, l23;
                split2(e4[0], e4[1], h01, l01);
                split2(e4[2], e4[3], h23, l23);
                ahx[half*2+0] = h01; ahx[half*2+1] = h23;
                alx[half*2+0] = l01; alx[half*2+1] = l23;
            }
            uint32_t bvh[4][4], bvl[4][4];
            #pragma unroll
            for (int nbp = 0; nbp < 4; nbp++) {
                const uint32_t boff = (uint32_t)(((kc2*16 + tk8 + l8)*72 + nbp*16 + tn8)*2);
                ldsm4t(bvh[nbp], aVH + boff);
                ldsm4t(bvl[nbp], aVL + boff);
            }
            #pragma unroll
            for (int nb = 0; nb < 8; nb++) {
                const int nbp = nb >> 1, sel = (nb & 1)*2;
                mma16816(acc_out[nb], ahx, &bvh[nbp][sel]);
                mma16816(acc_out[nb], ahx, &bvl[nbp][sel]);
                mma16816(acc_out[nb], alx, &bvh[nbp][sel]);
            }
        }
        __syncthreads();
    }

    // ---- epilogue ----
    s1 += __shfl_xor_sync(0xffffffffu, s1, 1);
    s1 += __shfl_xor_sync(0xffffffffu, s1, 2);
    s2 += __shfl_xor_sync(0xffffffffu, s2, 1);
    s2 += __shfl_xor_sync(0xffffffffu, s2, 2);
    const float rv1 = 1.0f / s1, rv2 = 1.0f / s2;
    if ((lane & 3) == 0) {
        g_rowinv[(size_t)bh*SEQ + q1] = rv1;
        g_rowinv[(size_t)bh*SEQ + q2] = rv2;
    }
    const int b = bh >> 3, h = bh & 7;
    #pragma unroll
    for (int nb = 0; nb < 8; nb++) {
        const int col = h*64 + nb*8 + c0;
        *(float2*)&out[((size_t)(b*SEQ + q1))*512 + col] =
            make_float2(acc_out[nb][0]*rv1, acc_out[nb][1]*rv1);
        *(float2*)&out[((size_t)(b*SEQ + q2))*512 + col] =
            make_float2(acc_out[nb][2]*rv2, acc_out[nb][3]*rv2);
    }

    // ---- signal chunk completion ----
    __threadfence();
    __syncthreads();
    if (tid == 0) atomicAdd(&g_done[chunk], 1);

    // ---- deferred norm duty: normalize slice idx of chunk-2 ----
    if (chunk >= 2) {
        const int nc = chunk - 2;
        if (tid == 0) {
            while (atomicAdd(&g_done[nc], 0) < 200) __nanosleep(128);
            __threadfence();
        }
        __syncthreads();
        norm_slice(nc, idx, p, tid);
    }
}

extern "C" void kernel_launch(void* const* d_in, const int* in_sizes, int n_in,
                              void* d_out, int out_size)
{
    const float* x  = (const float*)d_in[0];
    const float* wq = (const float*)d_in[1];
    const float* bq = (const float*)d_in[2];
    const float* wk = (const float*)d_in[3];
    const float* bk = (const float*)d_in[4];
    const float* wv = (const float*)d_in[5];
    const float* bv = (const float*)d_in[6];
    float* out = (float*)d_out;
    float* p   = out + OUT_ELEMS;

    cudaFuncSetAttribute(proj_kernel,          cudaFuncAttributeMaxDynamicSharedMemorySize, PJ_SMEM_BYTES);
    cudaFuncSetAttribute(attn_combined_kernel, cudaFuncAttributeMaxDynamicSharedMemorySize, FA_SMEM_BYTES);

    convert_w_kernel<<<1536, 256>>>(wq, wk, wv);
    proj_kernel<<<dim3(100, 4, 3), 256, PJ_SMEM_BYTES>>>(x, bq, bk, bv);
    attn_combined_kernel<<<2000, 128, FA_SMEM_BYTES>>>(p, out);
}

// round 15
// speedup vs baseline: 1.5887x; 1.5887x over previous
#include <cuda_runtime.h>
#include <cuda_fp16.h>
#include <cstdint>

#define SEQ 1600
#define BH  64
#define OUT_ELEMS (8*SEQ*512)

// -------------------- scratch --------------------
__device__ __half g_q[(size_t)BH*SEQ*64];
__device__ __half g_k[(size_t)BH*SEQ*64];
__device__ __half g_v[(size_t)BH*SEQ*64];    // [bh][s][d] natural
__device__ __half g_wt[3*512*256];           // [mat][n][k] transposed
__device__ float g_rowinv[(size_t)BH*SEQ];

// -------------------- mma.sync / ldmatrix --------------------
__device__ __forceinline__ uint32_t smem_u32(const void* p_) {
    uint32_t a;
    asm("{ .reg .u64 t; cvta.to.shared.u64 t, %1; cvt.u32.u64 %0, t; }" : "=r"(a) : "l"(p_));
    return a;
}
__device__ __forceinline__ void ldsm4(uint32_t* r, uint32_t addr) {
    asm volatile("ldmatrix.sync.aligned.m8n8.x4.shared.b16 {%0,%1,%2,%3}, [%4];"
                 : "=r"(r[0]), "=r"(r[1]), "=r"(r[2]), "=r"(r[3]) : "r"(addr));
}
__device__ __forceinline__ void ldsm4t(uint32_t* r, uint32_t addr) {
    asm volatile("ldmatrix.sync.aligned.m8n8.x4.trans.shared.b16 {%0,%1,%2,%3}, [%4];"
                 : "=r"(r[0]), "=r"(r[1]), "=r"(r[2]), "=r"(r[3]) : "r"(addr));
}
__device__ __forceinline__ void mma16816h(float* d, const uint32_t* a, const uint32_t* b) {
    asm volatile("mma.sync.aligned.m16n8k16.row.col.f32.f16.f16.f32 "
                 "{%0,%1,%2,%3}, {%4,%5,%6,%7}, {%8,%9}, {%0,%1,%2,%3};"
                 : "+f"(d[0]), "+f"(d[1]), "+f"(d[2]), "+f"(d[3])
                 : "r"(a[0]), "r"(a[1]), "r"(a[2]), "r"(a[3]), "r"(b[0]), "r"(b[1]));
}
__device__ __forceinline__ uint32_t h2u(float a, float b) {
    __half2 h = __floats2half2_rn(a, b);
    return *(uint32_t*)&h;
}

// ==================== K0: transpose + convert W ====================
__global__ __launch_bounds__(256) void convert_w_kernel(
    const float* __restrict__ wq, const float* __restrict__ wk, const float* __restrict__ wv)
{
    const int idx = blockIdx.x*256 + threadIdx.x;      // 0..393215
    const int mat = idx >> 17;
    const int rem = idx & 131071;
    const int k = rem >> 9, n = rem & 511;
    const float* w = (mat == 0) ? wq : ((mat == 1) ? wk : wv);
    g_wt[((size_t)mat << 17) + (size_t)n*256 + k] = __float2half(w[rem]);
}

// ==================== K1: QKV projection via fp16 mma ====================
// smem: X[128*72] + W[128*72] halves = 36864 B
#define PJ_TILE 9216
#define PJ_SMEM_BYTES (2*PJ_TILE*2)

__global__ __launch_bounds__(256, 2) void proj_kernel(
    const float* __restrict__ x,
    const float* __restrict__ bq, const float* __restrict__ bk, const float* __restrict__ bv)
{
    extern __shared__ __align__(16) __half sm[];
    __half* XS = sm;
    __half* WS = sm + PJ_TILE;

    const int tid = threadIdx.x, w = tid >> 5, lane = tid & 31;
    const int m0 = blockIdx.x*128, n0 = blockIdx.y*128, mat = blockIdx.z;
    const float* bb = (mat == 0) ? bq : ((mat == 1) ? bk : bv);
    const __half* wt = g_wt + ((size_t)mat << 17);

    float acc[16][4];
    #pragma unroll
    for (int i = 0; i < 16; i++)
        #pragma unroll
        for (int j = 0; j < 4; j++) acc[i][j] = 0.f;

    const uint32_t aXS = smem_u32(XS), aWS = smem_u32(WS);

    const int arow = lane & 15, ak8 = (lane >> 4)*8;
    const int mi = lane >> 3, l8 = lane & 7;
    const int brow8 = (mi >> 1)*8 + l8, bk8 = (mi & 1)*8;

    for (int kc = 0; kc < 256; kc += 64) {
        // X fp32 -> fp16 into smem
        #pragma unroll
        for (int j = 0; j < 8; j++) {
            const int idx = tid + j*256;           // 0..2047
            const int r = idx >> 4, c4 = idx & 15;
            const float4 v = *(const float4*)&x[(size_t)(m0 + r)*256 + kc + c4*4];
            *(uint2*)&XS[r*72 + c4*4] = make_uint2(h2u(v.x, v.y), h2u(v.z, v.w));
        }
        // W^T fp16 tile
        #pragma unroll
        for (int j = 0; j < 4; j++) {
            const int idx = tid + j*256;           // 0..1023
            const int r = idx >> 3, c8 = (idx & 7)*8;
            *(uint4*)&WS[r*72 + c8] = *(const uint4*)&wt[(size_t)(n0 + r)*256 + kc + c8];
        }
        __syncthreads();

        #pragma unroll
        for (int kc16 = 0; kc16 < 4; kc16++) {
            uint32_t ah[4];
            const uint32_t aoff = (uint32_t)(((w*16 + arow)*72 + kc16*16 + ak8)*2);
            ldsm4(ah, aXS + aoff);
            #pragma unroll
            for (int nbp = 0; nbp < 8; nbp++) {
                uint32_t bhf[4];
                const uint32_t boff = (uint32_t)(((nbp*16 + brow8)*72 + kc16*16 + bk8)*2);
                ldsm4(bhf, aWS + boff);
                #pragma unroll
                for (int half = 0; half < 2; half++)
                    mma16816h(acc[nbp*2 + half], ah, &bhf[half*2]);
            }
        }
        __syncthreads();
    }

    const int r0 = lane >> 2, c0 = (lane & 3)*2;
    const int m1 = m0 + w*16 + r0, m2 = m1 + 8;
    const int bI1 = m1 / SEQ, s1 = m1 % SEQ;
    const int bI2 = m2 / SEQ, s2 = m2 % SEQ;
    const float sc = (mat == 0) ? 0.125f : 1.0f;
    __half* dst = (mat == 0) ? g_q : ((mat == 1) ? g_k : g_v);

    #pragma unroll
    for (int nb = 0; nb < 16; nb++) {
        const int n = n0 + nb*8 + c0;
        const int h = n >> 6, d = n & 63;
        const float b0 = bb[n], b1 = bb[n + 1];
        #pragma unroll
        for (int rr = 0; rr < 2; rr++) {
            float v0 = (acc[nb][rr*2]     + b0) * sc;
            float v1 = (acc[nb][rr*2 + 1] + b1) * sc;
            if (mat == 2) { v0 = fmaxf(v0, 0.f); v1 = fmaxf(v1, 0.f); }
            const int bI = rr ? bI2 : bI1;
            const int s  = rr ? s2  : s1;
            *(uint32_t*)&dst[((size_t)(bI*8 + h)*SEQ + s)*64 + d] = h2u(v0, v1);
        }
    }
}

// ==================== K2: fused attention (fp16 single-MMA) ====================
// smem: Q[64*72] K[64*72] V[64*72] halves = 27648 B
#define FA_TILE 4608
#define FA_SMEM_BYTES (3*FA_TILE*2)

__global__ __launch_bounds__(128) void fused_attn_kernel(float* __restrict__ p,
                                                         float* __restrict__ out)
{
    extern __shared__ __align__(16) __half smf[];
    __half* QS = smf;
    __half* KS = smf + FA_TILE;
    __half* VS = smf + 2*FA_TILE;

    const int tid = threadIdx.x, w = tid >> 5, lane = tid & 31;
    const int qt = blockIdx.x, bh = blockIdx.y;
    const int q0 = qt*64;

    // ---- load Q tile once ----
    {
        const uint4* sq = (const uint4*)(g_q + ((size_t)bh*SEQ + q0)*64);
        #pragma unroll
        for (int it = 0; it < 4; it++) {
            const int i = tid + it*128;            // 0..511
            const int r = i >> 3, c8 = (i & 7)*8;
            *(uint4*)&QS[r*72 + c8] = sq[i];
        }
    }

    const uint32_t aQS = smem_u32(QS), aKS = smem_u32(KS), aVS = smem_u32(VS);

    const int arow = lane & 15, ak8 = (lane >> 4)*8;
    const int mi = lane >> 3, l8 = lane & 7;
    const int brow8 = (mi >> 1)*8 + l8, bk8 = (mi & 1)*8;
    const int tk8 = (mi & 1)*8, tn8 = (mi >> 1)*8;
    const int r0 = lane >> 2, c0 = (lane & 3)*2;

    const int q1 = q0 + w*16 + r0, q2 = q1 + 8;
    const int qf1 = q1 / 25, qf2 = q2 / 25;
    float* prow1 = p + ((size_t)bh*SEQ + q1)*SEQ;
    float* prow2 = p + ((size_t)bh*SEQ + q2)*SEQ;

    float acc_out[8][4];
    #pragma unroll
    for (int i = 0; i < 8; i++)
        #pragma unroll
        for (int j = 0; j < 4; j++) acc_out[i][j] = 0.f;
    float s1 = 0.f, s2 = 0.f;

    for (int c = 0; c < 25; c++) {
        const int s0 = c*64;
        // ---- load K and V tiles ([s][d] natural) ----
        #pragma unroll
        for (int it = 0; it < 4; it++) {
            const int i = tid + it*128;            // 0..511
            const int r = i >> 3, c8 = (i & 7)*8;
            const size_t gs = ((size_t)bh*SEQ + s0 + r)*64 + c8;
            *(uint4*)&KS[r*72 + c8] = *(const uint4*)&g_k[gs];
            *(uint4*)&VS[r*72 + c8] = *(const uint4*)&g_v[gs];
        }
        __syncthreads();

        // ---- QK^T ----
        float eacc[8][4];
        #pragma unroll
        for (int i = 0; i < 8; i++)
            #pragma unroll
            for (int j = 0; j < 4; j++) eacc[i][j] = 0.f;

        #pragma unroll
        for (int kc = 0; kc < 4; kc++) {
            uint32_t ah[4], bk[4][4];
            const uint32_t aoff = (uint32_t)(((w*16 + arow)*72 + kc*16 + ak8)*2);
            ldsm4(ah, aQS + aoff);
            #pragma unroll
            for (int nbp = 0; nbp < 4; nbp++) {
                const uint32_t boff = (uint32_t)(((nbp*16 + brow8)*72 + kc*16 + bk8)*2);
                ldsm4(bk[nbp], aKS + boff);
            }
            #pragma unroll
            for (int nb = 0; nb < 8; nb++)
                mma16816h(eacc[nb], ah, &bk[nb >> 1][(nb & 1)*2]);
        }

        // ---- mask + exp + store raw e + rowsum ----
        #pragma unroll
        for (int nb = 0; nb < 8; nb++) {
            const int k = s0 + nb*8 + c0;
            const int kfa = k / 25, kfb = (k + 1) / 25;
            float e0 = (qf1 != kfa || q1 == k  ) ? __expf(eacc[nb][0]) : 0.f;
            float e1 = (qf1 != kfb || q1 == k+1) ? __expf(eacc[nb][1]) : 0.f;
            float e2 = (qf2 != kfa || q2 == k  ) ? __expf(eacc[nb][2]) : 0.f;
            float e3 = (qf2 != kfb || q2 == k+1) ? __expf(eacc[nb][3]) : 0.f;
            s1 += e0 + e1; s2 += e2 + e3;
            *(float2*)&prow1[k] = make_float2(e0, e1);
            *(float2*)&prow2[k] = make_float2(e2, e3);
            eacc[nb][0] = e0; eacc[nb][1] = e1; eacc[nb][2] = e2; eacc[nb][3] = e3;
        }

        // ---- PV: A = e (in-register fp16 frags), B = V via ldmatrix.trans ----
        #pragma unroll
        for (int kc2 = 0; kc2 < 4; kc2++) {
            uint32_t ahx[4];
            #pragma unroll
            for (int half = 0; half < 2; half++) {
                const float* e4 = eacc[kc2*2 + half];
                ahx[half*2+0] = h2u(e4[0], e4[1]);
                ahx[half*2+1] = h2u(e4[2], e4[3]);
            }
            uint32_t bv[4][4];
            #pragma unroll
            for (int nbp = 0; nbp < 4; nbp++) {
                const uint32_t boff = (uint32_t)(((kc2*16 + tk8 + l8)*72 + nbp*16 + tn8)*2);
                ldsm4t(bv[nbp], aVS + boff);
            }
            #pragma unroll
            for (int nb = 0; nb < 8; nb++)
                mma16816h(acc_out[nb], ahx, &bv[nb >> 1][(nb & 1)*2]);
        }
        __syncthreads();
    }

    // ---- epilogue ----
    s1 += __shfl_xor_sync(0xffffffffu, s1, 1);
    s1 += __shfl_xor_sync(0xffffffffu, s1, 2);
    s2 += __shfl_xor_sync(0xffffffffu, s2, 1);
    s2 += __shfl_xor_sync(0xffffffffu, s2, 2);
    const float rv1 = 1.0f / s1, rv2 = 1.0f / s2;
    if ((lane & 3) == 0) {
        g_rowinv[(size_t)bh*SEQ + q1] = rv1;
        g_rowinv[(size_t)bh*SEQ + q2] = rv2;
    }
    const int b = bh >> 3, h = bh & 7;
    #pragma unroll
    for (int nb = 0; nb < 8; nb++) {
        const int col = h*64 + nb*8 + c0;
        *(float2*)&out[((size_t)(b*SEQ + q1))*512 + col] =
            make_float2(acc_out[nb][0]*rv1, acc_out[nb][1]*rv1);
        *(float2*)&out[((size_t)(b*SEQ + q2))*512 + col] =
            make_float2(acc_out[nb][2]*rv2, acc_out[nb][3]*rv2);
    }
}

// ==================== K3: normalize p (streaming) ====================
__global__ __launch_bounds__(256) void norm_kernel(float* __restrict__ p)
{
    const size_t i4 = (size_t)blockIdx.x*256 + threadIdx.x;
    const int row = (int)(i4 / 400);
    const float rv = g_rowinv[row];
    float4 v = ((const float4*)p)[i4];
    v.x *= rv; v.y *= rv; v.z *= rv; v.w *= rv;
    ((float4*)p)[i4] = v;
}

extern "C" void kernel_launch(void* const* d_in, const int* in_sizes, int n_in,
                              void* d_out, int out_size)
{
    const float* x  = (const float*)d_in[0];
    const float* wq = (const float*)d_in[1];
    const float* bq = (const float*)d_in[2];
    const float* wk = (const float*)d_in[3];
    const float* bk = (const float*)d_in[4];
    const float* wv = (const float*)d_in[5];
    const float* bv = (const float*)d_in[6];
    float* out = (float*)d_out;
    float* p   = out + OUT_ELEMS;

    cudaFuncSetAttribute(proj_kernel,       cudaFuncAttributeMaxDynamicSharedMemorySize, PJ_SMEM_BYTES);
    cudaFuncSetAttribute(fused_attn_kernel, cudaFuncAttributeMaxDynamicSharedMemorySize, FA_SMEM_BYTES);

    convert_w_kernel<<<1536, 256>>>(wq, wk, wv);
    proj_kernel<<<dim3(100, 4, 3), 256, PJ_SMEM_BYTES>>>(x, bq, bk, bv);
    fused_attn_kernel<<<dim3(25, BH), 128, FA_SMEM_BYTES>>>(p, out);
    norm_kernel<<<dim3((int)(((size_t)BH*SEQ*400 + 255)/256)), 256>>>(p);
}